// round 6
// baseline (speedup 1.0000x reference)
#include <cuda_runtime.h>

// Problem constants
#define BATCH   8
#define CDIM    512
#define SEQ     1024      // H*W = 32*32
#define NHEADS  8
#define HDIM    64
#define SCALE   0.125f    // 1/sqrt(64)

// Scratch for projected Q, K, V in [b][h][s][d] layout (fp32).
// 8*512*1024 = 4,194,304 floats each (16 MB).
__device__ float g_Q[BATCH * CDIM * SEQ];
__device__ float g_K[BATCH * CDIM * SEQ];
__device__ float g_V[BATCH * CDIM * SEQ];

// ---------------------------------------------------------------------------
// Projection GEMM:  out[m][n] = sum_k A[m][k] * W[k][n + proj*512] + bias
//   m = b*1024 + s,  A[m][k] = src[b*524288 + k*1024 + s]   (NCHW transpose)
//   BM=128, BN=128, BK=8, 256 threads, 8x8 micro-tile.
//   Output written to g_Q/g_K/g_V as [b][h][s][d] (h = n>>6, d = n&63).
// ---------------------------------------------------------------------------
__global__ void __launch_bounds__(256, 2)
proj_kernel(const float* __restrict__ q_in,
            const float* __restrict__ kv_in,
            const float* __restrict__ W,
            const float* __restrict__ bias)
{
    __shared__ float As[8][128];
    __shared__ float Bs[8][128];

    const int proj = blockIdx.z;                   // 0=Q, 1=K, 2=V
    const float* src = (proj == 0) ? q_in : kv_in;
    float* dst = (proj == 0) ? g_Q : ((proj == 1) ? g_K : g_V);

    const int tid = threadIdx.x;
    const int tx  = tid & 15;        // n direction (8 cols each)
    const int ty  = tid >> 4;        // m direction (8 rows each)

    const int b  = blockIdx.y >> 3;             // 128-row tiles never straddle batch
    const int s0 = (blockIdx.y & 7) << 7;
    const int n0 = blockIdx.x << 7;

    const float* Abase = src + b * (CDIM * SEQ) + s0;      // + k*1024 + m
    const float* Bbase = W + proj * 512 + n0;              // + k*1536 + n

    const int ka = tid >> 5;             // 0..7
    const int ma = (tid & 31) << 2;      // 0..124  (float4)

    float acc[8][8];
#pragma unroll
    for (int i = 0; i < 8; i++)
#pragma unroll
        for (int j = 0; j < 8; j++) acc[i][j] = 0.0f;

    for (int k0 = 0; k0 < CDIM; k0 += 8) {
        // issue global loads before barrier (overlap with prev compute)
        float4 av = *(const float4*)(Abase + (k0 + ka) * SEQ + ma);
        float4 bv = *(const float4*)(Bbase + (k0 + ka) * (3 * CDIM) + ma);
        __syncthreads();
        *(float4*)&As[ka][ma] = av;
        *(float4*)&Bs[ka][ma] = bv;
        __syncthreads();

#pragma unroll
        for (int kk = 0; kk < 8; kk++) {
            float a[8], bb[8];
            *(float4*)(a + 0) = *(const float4*)&As[kk][ty * 8 + 0];
            *(float4*)(a + 4) = *(const float4*)&As[kk][ty * 8 + 4];
            *(float4*)(bb + 0) = *(const float4*)&Bs[kk][tx * 8 + 0];
            *(float4*)(bb + 4) = *(const float4*)&Bs[kk][tx * 8 + 4];
#pragma unroll
            for (int i = 0; i < 8; i++)
#pragma unroll
                for (int j = 0; j < 8; j++)
                    acc[i][j] += a[i] * bb[j];
        }
    }

    // epilogue: add bias, write to [b][h][s][d]
    const int nbase = n0 + tx * 8;           // multiple of 8 -> stays in one head
    const int h  = nbase >> 6;
    const int d0 = nbase & 63;
    float bv[8];
#pragma unroll
    for (int j = 0; j < 8; j++) bv[j] = bias[proj * 512 + nbase + j];

    float* obase = dst + b * (CDIM * SEQ) + h * (SEQ * HDIM) + d0;
#pragma unroll
    for (int i = 0; i < 8; i++) {
        const int s = s0 + ty * 8 + i;
        float4 v0, v1;
        v0.x = acc[i][0] + bv[0]; v0.y = acc[i][1] + bv[1];
        v0.z = acc[i][2] + bv[2]; v0.w = acc[i][3] + bv[3];
        v1.x = acc[i][4] + bv[4]; v1.y = acc[i][5] + bv[5];
        v1.z = acc[i][6] + bv[6]; v1.w = acc[i][7] + bv[7];
        *(float4*)(obase + s * HDIM + 0) = v0;
        *(float4*)(obase + s * HDIM + 4) = v1;
    }
}

// ---------------------------------------------------------------------------
// Flash attention: one block per (q-tile of 64 rows, b*h).
//   256 threads as 16x16 grid, 4x4 register tiles.
//   Online softmax state (m, l) per row, reduced over the 16-thread row group
//   with shfl_xor butterflies.
// Dynamic smem layout (floats):
//   Qt   [64][64]  : Q^T tile, pre-scaled        (4096)
//   KsPt [64][65]  : K tile [key][d] padded, later reused as P^T[key][row],
//                    finally reused as O^T[d][row] for coalesced stores (4160)
//   Vs   [64][64]  : V tile [key][d]             (4096)
// ---------------------------------------------------------------------------
#define ATTN_SMEM_FLOATS (4096 + 4160 + 4096)

__global__ void __launch_bounds__(256)
attn_kernel(float* __restrict__ out)
{
    extern __shared__ float sm[];
    float* Qt   = sm;                 // [d][row]
    float* KsPt = sm + 4096;          // [key][d(+pad)] / [key][row(+pad)]
    float* Vs   = sm + 4096 + 4160;   // [key][d]

    const int tid = threadIdx.x;
    const int tx  = tid & 15;         // key-cols / d-cols (4 each)
    const int ty  = tid >> 4;         // q-rows (4 each)

    const int bh = blockIdx.y;
    const int q0 = blockIdx.x << 6;
    const float* Qp = g_Q + bh * (SEQ * HDIM);
    const float* Kp = g_K + bh * (SEQ * HDIM);
    const float* Vp = g_V + bh * (SEQ * HDIM);

    // Load Q tile transposed, pre-scaled by 1/sqrt(d)
#pragma unroll
    for (int it = 0; it < 4; it++) {
        const int id  = tid + it * 256;
        const int row = id >> 4;
        const int d0  = (id & 15) << 2;
        float4 qv = *(const float4*)(Qp + (q0 + row) * HDIM + d0);
        Qt[(d0 + 0) * 64 + row] = qv.x * SCALE;
        Qt[(d0 + 1) * 64 + row] = qv.y * SCALE;
        Qt[(d0 + 2) * 64 + row] = qv.z * SCALE;
        Qt[(d0 + 3) * 64 + row] = qv.w * SCALE;
    }

    float o_acc[4][4];
    float m_i[4], l_i[4];
#pragma unroll
    for (int i = 0; i < 4; i++) {
        m_i[i] = -1e30f;
        l_i[i] = 0.0f;
#pragma unroll
        for (int j = 0; j < 4; j++) o_acc[i][j] = 0.0f;
    }

    for (int kt = 0; kt < 16; kt++) {
        const int key0 = kt << 6;
        __syncthreads();   // prev PV / Q-load done; KsPt & Vs free

        // Load K tile (padded rows) and V tile
#pragma unroll
        for (int it = 0; it < 4; it++) {
            const int id   = tid + it * 256;
            const int krow = id >> 4;
            const int d0   = (id & 15) << 2;
            float4 kv = *(const float4*)(Kp + (key0 + krow) * HDIM + d0);
            KsPt[krow * 65 + d0 + 0] = kv.x;
            KsPt[krow * 65 + d0 + 1] = kv.y;
            KsPt[krow * 65 + d0 + 2] = kv.z;
            KsPt[krow * 65 + d0 + 3] = kv.w;
            float4 vv = *(const float4*)(Vp + (key0 + krow) * HDIM + d0);
            *(float4*)&Vs[krow * 64 + d0] = vv;
        }
        __syncthreads();

        // S = Q * K^T  (already scaled)
        float s_acc[4][4];
#pragma unroll
        for (int i = 0; i < 4; i++)
#pragma unroll
            for (int j = 0; j < 4; j++) s_acc[i][j] = 0.0f;

#pragma unroll 16
        for (int kk = 0; kk < 64; kk++) {
            float4 a = *(const float4*)(Qt + kk * 64 + ty * 4);
            float b0 = KsPt[(tx * 4 + 0) * 65 + kk];
            float b1 = KsPt[(tx * 4 + 1) * 65 + kk];
            float b2 = KsPt[(tx * 4 + 2) * 65 + kk];
            float b3 = KsPt[(tx * 4 + 3) * 65 + kk];
            s_acc[0][0] += a.x * b0; s_acc[0][1] += a.x * b1;
            s_acc[0][2] += a.x * b2; s_acc[0][3] += a.x * b3;
            s_acc[1][0] += a.y * b0; s_acc[1][1] += a.y * b1;
            s_acc[1][2] += a.y * b2; s_acc[1][3] += a.y * b3;
            s_acc[2][0] += a.z * b0; s_acc[2][1] += a.z * b1;
            s_acc[2][2] += a.z * b2; s_acc[2][3] += a.z * b3;
            s_acc[3][0] += a.w * b0; s_acc[3][1] += a.w * b1;
            s_acc[3][2] += a.w * b2; s_acc[3][3] += a.w * b3;
        }

        // Online softmax
        float rm[4], rs[4], alpha[4];
#pragma unroll
        for (int i = 0; i < 4; i++) {
            rm[i] = fmaxf(fmaxf(s_acc[i][0], s_acc[i][1]),
                          fmaxf(s_acc[i][2], s_acc[i][3]));
        }
#pragma unroll
        for (int msk = 1; msk < 16; msk <<= 1)
#pragma unroll
            for (int i = 0; i < 4; i++)
                rm[i] = fmaxf(rm[i], __shfl_xor_sync(0xffffffffu, rm[i], msk));

#pragma unroll
        for (int i = 0; i < 4; i++) {
            float mn = fmaxf(m_i[i], rm[i]);
            alpha[i] = __expf(m_i[i] - mn);
            m_i[i] = mn;
        }
#pragma unroll
        for (int i = 0; i < 4; i++) {
#pragma unroll
            for (int j = 0; j < 4; j++)
                s_acc[i][j] = __expf(s_acc[i][j] - m_i[i]);
            rs[i] = s_acc[i][0] + s_acc[i][1] + s_acc[i][2] + s_acc[i][3];
        }
#pragma unroll
        for (int msk = 1; msk < 16; msk <<= 1)
#pragma unroll
            for (int i = 0; i < 4; i++)
                rs[i] += __shfl_xor_sync(0xffffffffu, rs[i], msk);
#pragma unroll
        for (int i = 0; i < 4; i++) {
            l_i[i] = l_i[i] * alpha[i] + rs[i];
#pragma unroll
            for (int j = 0; j < 4; j++) o_acc[i][j] *= alpha[i];
        }

        __syncthreads();   // everyone done reading K from KsPt
        // Stage P^T[key][row]
#pragma unroll
        for (int j = 0; j < 4; j++)
#pragma unroll
            for (int i = 0; i < 4; i++)
                KsPt[(tx * 4 + j) * 65 + ty * 4 + i] = s_acc[i][j];
        __syncthreads();

        // O += P * V
#pragma unroll 16
        for (int kk = 0; kk < 64; kk++) {
            float4 bv = *(const float4*)(Vs + kk * 64 + tx * 4);
            float a0 = KsPt[kk * 65 + ty * 4 + 0];
            float a1 = KsPt[kk * 65 + ty * 4 + 1];
            float a2 = KsPt[kk * 65 + ty * 4 + 2];
            float a3 = KsPt[kk * 65 + ty * 4 + 3];
            o_acc[0][0] += a0 * bv.x; o_acc[0][1] += a0 * bv.y;
            o_acc[0][2] += a0 * bv.z; o_acc[0][3] += a0 * bv.w;
            o_acc[1][0] += a1 * bv.x; o_acc[1][1] += a1 * bv.y;
            o_acc[1][2] += a1 * bv.z; o_acc[1][3] += a1 * bv.w;
            o_acc[2][0] += a2 * bv.x; o_acc[2][1] += a2 * bv.y;
            o_acc[2][2] += a2 * bv.z; o_acc[2][3] += a2 * bv.w;
            o_acc[3][0] += a3 * bv.x; o_acc[3][1] += a3 * bv.y;
            o_acc[3][2] += a3 * bv.z; o_acc[3][3] += a3 * bv.w;
        }
    }

    // Normalize
#pragma unroll
    for (int i = 0; i < 4; i++) {
        float inv = 1.0f / l_i[i];
#pragma unroll
        for (int j = 0; j < 4; j++) o_acc[i][j] *= inv;
    }

    // Transpose through smem for coalesced [b][c][s] stores
    __syncthreads();
#pragma unroll
    for (int j = 0; j < 4; j++)
#pragma unroll
        for (int i = 0; i < 4; i++)
            KsPt[(tx * 4 + j) * 65 + ty * 4 + i] = o_acc[i][j];   // O^T[d][row]
    __syncthreads();

    const int b = bh >> 3, h = bh & 7;
    float* obase = out + b * (CDIM * SEQ) + (h * HDIM) * SEQ + q0;
#pragma unroll
    for (int it = 0; it < 4; it++) {
        const int id = tid + it * 256;
        const int d  = id >> 4;
        const int r0 = (id & 15) << 2;
        float4 v;
        v.x = KsPt[d * 65 + r0 + 0];
        v.y = KsPt[d * 65 + r0 + 1];
        v.z = KsPt[d * 65 + r0 + 2];
        v.w = KsPt[d * 65 + r0 + 3];
        *(float4*)(obase + d * SEQ + r0) = v;
    }
}

// ---------------------------------------------------------------------------
extern "C" void kernel_launch(void* const* d_in, const int* in_sizes, int n_in,
                              void* d_out, int out_size)
{
    const float* q_in  = (const float*)d_in[0];   // query     [8,512,32,32]
    const float* kv_in = (const float*)d_in[1];   // key_value [8,512,32,32]
    const float* W     = (const float*)d_in[2];   // W_qkv     [512,1536]
    const float* bias  = (const float*)d_in[3];   // b_qkv     [1536]
    float* out = (float*)d_out;

    cudaFuncSetAttribute(attn_kernel,
                         cudaFuncAttributeMaxDynamicSharedMemorySize,
                         ATTN_SMEM_FLOATS * (int)sizeof(float));

    proj_kernel<<<dim3(4, 64, 3), 256>>>(q_in, kv_in, W, bias);
    attn_kernel<<<dim3(16, 64), 256, ATTN_SMEM_FLOATS * sizeof(float)>>>(out);
}

// round 7
// speedup vs baseline: 1.1806x; 1.1806x over previous
#include <cuda_runtime.h>

// Problem constants
#define BATCH   8
#define CDIM    512
#define SEQ     1024      // H*W = 32*32
#define NHEADS  8
#define HDIM    64
#define SCALE   0.125f    // 1/sqrt(64)
#define LOG2E   1.44269504088896340736f

typedef unsigned long long ull;
union F2 { ull u; float2 f; };

__device__ __forceinline__ ull pack2(float lo, float hi) {
    ull r; asm("mov.b64 %0, {%1, %2};" : "=l"(r) : "f"(lo), "f"(hi)); return r;
}
__device__ __forceinline__ void fma2(ull &d, ull a, ull b) {
    asm("fma.rn.f32x2 %0, %1, %2, %0;" : "+l"(d) : "l"(a), "l"(b));
}
__device__ __forceinline__ void mul2(ull &d, ull a) {
    asm("mul.rn.f32x2 %0, %1, %2;" : "=l"(d) : "l"(d), "l"(a));
}
__device__ __forceinline__ float ex2(float x) {
    float r; asm("ex2.approx.f32 %0, %1;" : "=f"(r) : "f"(x)); return r;
}

// Scratch for projected Q, K, V in [b][h][s][d] layout (fp32). 16 MB each.
__device__ float g_Q[BATCH * CDIM * SEQ];
__device__ float g_K[BATCH * CDIM * SEQ];
__device__ float g_V[BATCH * CDIM * SEQ];

// ---------------------------------------------------------------------------
// Projection GEMM with packed f32x2 FMAs.
//   BM=128, BN=128, BK=8, 256 threads, 8x8 micro-tile, accumulators packed
//   in pairs along n (column pairs come free from LDS.128 of Bs; the a value
//   is splatted once per row per kk).
// ---------------------------------------------------------------------------
__global__ void __launch_bounds__(256, 2)
proj_kernel(const float* __restrict__ q_in,
            const float* __restrict__ kv_in,
            const float* __restrict__ W,
            const float* __restrict__ bias)
{
    __shared__ float As[8][128];
    __shared__ float Bs[8][128];

    const int proj = blockIdx.z;                   // 0=Q, 1=K, 2=V
    const float* src = (proj == 0) ? q_in : kv_in;
    float* dst = (proj == 0) ? g_Q : ((proj == 1) ? g_K : g_V);

    const int tid = threadIdx.x;
    const int tx  = tid & 15;        // n direction (8 cols each)
    const int ty  = tid >> 4;        // m direction (8 rows each)

    const int b  = blockIdx.y >> 3;
    const int s0 = (blockIdx.y & 7) << 7;
    const int n0 = blockIdx.x << 7;

    const float* Abase = src + b * (CDIM * SEQ) + s0;
    const float* Bbase = W + proj * 512 + n0;

    const int ka = tid >> 5;             // 0..7
    const int ma = (tid & 31) << 2;      // 0..124

    F2 acc2[8][4];                       // [row][col-pair]
#pragma unroll
    for (int i = 0; i < 8; i++)
#pragma unroll
        for (int j = 0; j < 4; j++) acc2[i][j].u = 0ull;

    for (int k0 = 0; k0 < CDIM; k0 += 8) {
        float4 av = *(const float4*)(Abase + (k0 + ka) * SEQ + ma);
        float4 bv = *(const float4*)(Bbase + (k0 + ka) * (3 * CDIM) + ma);
        __syncthreads();
        *(float4*)&As[ka][ma] = av;
        *(float4*)&Bs[ka][ma] = bv;
        __syncthreads();

#pragma unroll
        for (int kk = 0; kk < 8; kk++) {
            // b: 4 column-pairs straight out of LDS.128
            ulonglong2 b01 = *(const ulonglong2*)&Bs[kk][tx * 8];
            ulonglong2 b23 = *(const ulonglong2*)&Bs[kk][tx * 8 + 4];
            ull b2[4] = { b01.x, b01.y, b23.x, b23.y };
            // a: 8 row values, splatted
            float4 a0 = *(const float4*)&As[kk][ty * 8];
            float4 a1 = *(const float4*)&As[kk][ty * 8 + 4];
            ull as_[8] = { pack2(a0.x, a0.x), pack2(a0.y, a0.y),
                           pack2(a0.z, a0.z), pack2(a0.w, a0.w),
                           pack2(a1.x, a1.x), pack2(a1.y, a1.y),
                           pack2(a1.z, a1.z), pack2(a1.w, a1.w) };
#pragma unroll
            for (int i = 0; i < 8; i++)
#pragma unroll
                for (int j = 0; j < 4; j++)
                    fma2(acc2[i][j].u, as_[i], b2[j]);
        }
    }

    // epilogue: add bias, write to [b][h][s][d]
    const int nbase = n0 + tx * 8;           // multiple of 8 -> one head
    const int h  = nbase >> 6;
    const int d0 = nbase & 63;
    float bv[8];
#pragma unroll
    for (int j = 0; j < 8; j++) bv[j] = bias[proj * 512 + nbase + j];

    float* obase = dst + b * (CDIM * SEQ) + h * (SEQ * HDIM) + d0;
#pragma unroll
    for (int i = 0; i < 8; i++) {
        const int s = s0 + ty * 8 + i;
        float4 v0, v1;
        v0.x = acc2[i][0].f.x + bv[0]; v0.y = acc2[i][0].f.y + bv[1];
        v0.z = acc2[i][1].f.x + bv[2]; v0.w = acc2[i][1].f.y + bv[3];
        v1.x = acc2[i][2].f.x + bv[4]; v1.y = acc2[i][2].f.y + bv[5];
        v1.z = acc2[i][3].f.x + bv[6]; v1.w = acc2[i][3].f.y + bv[7];
        *(float4*)(obase + s * HDIM + 0) = v0;
        *(float4*)(obase + s * HDIM + 4) = v1;
    }
}

// ---------------------------------------------------------------------------
// Flash attention, 128 threads, 64x64 tiles, 8x4 per-thread micro-tile with
// f32x2-packed accumulators (packed along the q-row dimension, which is
// contiguous in Qt / Pt so the a-operand pairs come free from LDS.128).
// Softmax runs in the exp2 domain (log2e folded into the Q scale).
//
// Dynamic smem (floats):
//   Qt  [64][64]        Q^T tile, pre-scaled by SCALE*log2e          (4096)
//   Ks  [64][65] K tile [key][d], reused as P^T[key][row] stride 68,
//                finally as O^T[d][row] stride 68                    (4352)
//   Vs  [64][64]        V tile [key][d]                              (4096)
// ---------------------------------------------------------------------------
#define ATTN_SMEM_FLOATS (4096 + 4352 + 4096)

__global__ void __launch_bounds__(128)
attn_kernel(float* __restrict__ out)
{
    extern __shared__ float sm[];
    float* Qt = sm;                 // [d][row], stride 64
    float* Ks = sm + 4096;          // [key][d] stride 65 / P^T,O^T stride 68
    float* Vs = sm + 8448;          // [key][d] stride 64

    const int tid = threadIdx.x;
    const int tx  = tid & 15;       // 4 keys / 4 d-cols
    const int ty  = tid >> 4;       // 0..7 -> 8 q-rows (ty*8 ..)

    const int bh = blockIdx.y;
    const int q0 = blockIdx.x << 6;
    const float* Qp = g_Q + bh * (SEQ * HDIM);
    const float* Kp = g_K + bh * (SEQ * HDIM);
    const float* Vp = g_V + bh * (SEQ * HDIM);

    const float qscale = SCALE * LOG2E;

    // Load Q tile transposed, pre-scaled
#pragma unroll
    for (int it = 0; it < 8; it++) {
        const int id  = tid + it * 128;
        const int row = id >> 4;
        const int d0  = (id & 15) << 2;
        float4 qv = *(const float4*)(Qp + (q0 + row) * HDIM + d0);
        Qt[(d0 + 0) * 64 + row] = qv.x * qscale;
        Qt[(d0 + 1) * 64 + row] = qv.y * qscale;
        Qt[(d0 + 2) * 64 + row] = qv.z * qscale;
        Qt[(d0 + 3) * 64 + row] = qv.w * qscale;
    }

    F2 o2[4][4];                    // [row-pair][d-col]
    float m_i[8], l_i[8];
#pragma unroll
    for (int p = 0; p < 4; p++)
#pragma unroll
        for (int j = 0; j < 4; j++) o2[p][j].u = 0ull;
#pragma unroll
    for (int i = 0; i < 8; i++) { m_i[i] = -1e30f; l_i[i] = 0.0f; }

    for (int kt = 0; kt < 16; kt++) {
        const int key0 = kt << 6;
        __syncthreads();            // prev PV done reading Ks/Vs

        // Load K (stride 65, scalar stores) and V tiles
#pragma unroll
        for (int it = 0; it < 8; it++) {
            const int id   = tid + it * 128;
            const int krow = id >> 4;
            const int d0   = (id & 15) << 2;
            float4 kv = *(const float4*)(Kp + (key0 + krow) * HDIM + d0);
            Ks[krow * 65 + d0 + 0] = kv.x;
            Ks[krow * 65 + d0 + 1] = kv.y;
            Ks[krow * 65 + d0 + 2] = kv.z;
            Ks[krow * 65 + d0 + 3] = kv.w;
            float4 vv = *(const float4*)(Vp + (key0 + krow) * HDIM + d0);
            *(float4*)&Vs[krow * 64 + d0] = vv;
        }
        __syncthreads();

        // ---- S = Q*K^T (log2 domain), 8 rows x 4 keys, packed over rows ----
        F2 s2[4][4];
#pragma unroll
        for (int p = 0; p < 4; p++)
#pragma unroll
            for (int j = 0; j < 4; j++) s2[p][j].u = 0ull;

#pragma unroll 8
        for (int kk = 0; kk < 64; kk++) {
            ulonglong2 a01 = *(const ulonglong2*)(Qt + kk * 64 + ty * 8);
            ulonglong2 a23 = *(const ulonglong2*)(Qt + kk * 64 + ty * 8 + 4);
            float bb0 = Ks[(tx * 4 + 0) * 65 + kk];
            float bb1 = Ks[(tx * 4 + 1) * 65 + kk];
            float bb2 = Ks[(tx * 4 + 2) * 65 + kk];
            float bb3 = Ks[(tx * 4 + 3) * 65 + kk];
            ull b2[4] = { pack2(bb0, bb0), pack2(bb1, bb1),
                          pack2(bb2, bb2), pack2(bb3, bb3) };
            ull a2[4] = { a01.x, a01.y, a23.x, a23.y };
#pragma unroll
            for (int p = 0; p < 4; p++)
#pragma unroll
                for (int j = 0; j < 4; j++)
                    fma2(s2[p][j].u, a2[p], b2[j]);
        }

        // ---- Online softmax (exp2 domain) ----
        float rm[8], rs[8], alpha[8];
#pragma unroll
        for (int p = 0; p < 4; p++) {
            rm[2*p]   = fmaxf(fmaxf(s2[p][0].f.x, s2[p][1].f.x),
                              fmaxf(s2[p][2].f.x, s2[p][3].f.x));
            rm[2*p+1] = fmaxf(fmaxf(s2[p][0].f.y, s2[p][1].f.y),
                              fmaxf(s2[p][2].f.y, s2[p][3].f.y));
        }
#pragma unroll
        for (int msk = 1; msk < 16; msk <<= 1)
#pragma unroll
            for (int i = 0; i < 8; i++)
                rm[i] = fmaxf(rm[i], __shfl_xor_sync(0xffffffffu, rm[i], msk));

#pragma unroll
        for (int i = 0; i < 8; i++) {
            float mn = fmaxf(m_i[i], rm[i]);
            alpha[i] = ex2(m_i[i] - mn);
            m_i[i] = mn;
        }
#pragma unroll
        for (int p = 0; p < 4; p++) {
#pragma unroll
            for (int j = 0; j < 4; j++) {
                s2[p][j].f.x = ex2(s2[p][j].f.x - m_i[2*p]);
                s2[p][j].f.y = ex2(s2[p][j].f.y - m_i[2*p+1]);
            }
            rs[2*p]   = s2[p][0].f.x + s2[p][1].f.x + s2[p][2].f.x + s2[p][3].f.x;
            rs[2*p+1] = s2[p][0].f.y + s2[p][1].f.y + s2[p][2].f.y + s2[p][3].f.y;
        }
#pragma unroll
        for (int msk = 1; msk < 16; msk <<= 1)
#pragma unroll
            for (int i = 0; i < 8; i++)
                rs[i] += __shfl_xor_sync(0xffffffffu, rs[i], msk);
#pragma unroll
        for (int i = 0; i < 8; i++)
            l_i[i] = l_i[i] * alpha[i] + rs[i];
#pragma unroll
        for (int p = 0; p < 4; p++) {
            ull a2p = pack2(alpha[2*p], alpha[2*p+1]);
#pragma unroll
            for (int j = 0; j < 4; j++) mul2(o2[p][j].u, a2p);
        }

        __syncthreads();            // everyone done reading K from Ks
        // Stage P^T[key][row] with stride 68 (16B-aligned rows), 64-bit stores
#pragma unroll
        for (int j = 0; j < 4; j++)
#pragma unroll
            for (int p = 0; p < 4; p++)
                *(ull*)(Ks + (tx * 4 + j) * 68 + ty * 8 + 2 * p) = s2[p][j].u;
        __syncthreads();

        // ---- O += P*V, packed over rows (a pairs free from P^T) ----
#pragma unroll 8
        for (int kk = 0; kk < 64; kk++) {
            ulonglong2 a01 = *(const ulonglong2*)(Ks + kk * 68 + ty * 8);
            ulonglong2 a23 = *(const ulonglong2*)(Ks + kk * 68 + ty * 8 + 4);
            float4 v = *(const float4*)(Vs + kk * 64 + tx * 4);
            ull b2[4] = { pack2(v.x, v.x), pack2(v.y, v.y),
                          pack2(v.z, v.z), pack2(v.w, v.w) };
            ull a2[4] = { a01.x, a01.y, a23.x, a23.y };
#pragma unroll
            for (int p = 0; p < 4; p++)
#pragma unroll
                for (int j = 0; j < 4; j++)
                    fma2(o2[p][j].u, a2[p], b2[j]);
        }
    }

    // Normalize
#pragma unroll
    for (int p = 0; p < 4; p++) {
        ull inv2 = pack2(1.0f / l_i[2*p], 1.0f / l_i[2*p+1]);
#pragma unroll
        for (int j = 0; j < 4; j++) mul2(o2[p][j].u, inv2);
    }

    // Transpose through smem (O^T[d][row], stride 68) for coalesced stores
    __syncthreads();
#pragma unroll
    for (int j = 0; j < 4; j++)
#pragma unroll
        for (int p = 0; p < 4; p++)
            *(ull*)(Ks + (tx * 4 + j) * 68 + ty * 8 + 2 * p) = o2[p][j].u;
    __syncthreads();

    const int b = bh >> 3, h = bh & 7;
    float* obase = out + b * (CDIM * SEQ) + (h * HDIM) * SEQ + q0;
#pragma unroll
    for (int it = 0; it < 8; it++) {
        const int id = tid + it * 128;
        const int d  = id >> 4;
        const int r0 = (id & 15) << 2;
        float4 v = *(const float4*)(Ks + d * 68 + r0);
        *(float4*)(obase + d * SEQ + r0) = v;
    }
}

// ---------------------------------------------------------------------------
extern "C" void kernel_launch(void* const* d_in, const int* in_sizes, int n_in,
                              void* d_out, int out_size)
{
    const float* q_in  = (const float*)d_in[0];   // query     [8,512,32,32]
    const float* kv_in = (const float*)d_in[1];   // key_value [8,512,32,32]
    const float* W     = (const float*)d_in[2];   // W_qkv     [512,1536]
    const float* bias  = (const float*)d_in[3];   // b_qkv     [1536]
    float* out = (float*)d_out;

    cudaFuncSetAttribute(attn_kernel,
                         cudaFuncAttributeMaxDynamicSharedMemorySize,
                         ATTN_SMEM_FLOATS * (int)sizeof(float));

    proj_kernel<<<dim3(4, 64, 3), 256>>>(q_in, kv_in, W, bias);
    attn_kernel<<<dim3(16, 64), 128, ATTN_SMEM_FLOATS * sizeof(float)>>>(out);
}